// round 11
// baseline (speedup 1.0000x reference)
#include <cuda_runtime.h>
#include <cuda_fp16.h>
#include <cstdint>
#include <cstddef>

#define B_  2
#define S_  2048
#define H_  1024
#define NH_ 16
#define HD_ 64
#define M_  (B_ * S_)   // 4096 rows

// Scratch (allocation-free rule: __device__ globals)
// All k-dimensions stored pi-permuted within 16-element blocks:
//   new order = 0,1,8,9, 2,3,10,11, 4,5,12,13, 6,7,14,15
__device__ __align__(16) __half g_INh[(size_t)3 * M_ * H_];            // q,k,v inputs fp16 (H pi)
__device__ __align__(16) __half g_Wh[(size_t)4 * H_ * H_];             // weights fp16 (k pi)
__device__ __align__(16) __half g_Qh[(size_t)M_ * H_];                 // [b][s][h] fp16 (hd pi)
__device__ __align__(16) __half g_Kh[(size_t)M_ * H_];                 // [b][s][h] fp16 (hd pi)
__device__ __align__(16) __half g_Vt[(size_t)B_ * NH_ * HD_ * S_];     // [b][h][hd][s] fp16 (s pi)
__device__ __align__(16) __half g_AOh[(size_t)M_ * H_];                // attn out fp16 (H pi)
__device__ __align__(16) float  g_FM[(size_t)B_ * S_ * S_];            // -1 or sm*0.125

// ---------------------------------------------------------------------------
__device__ __forceinline__ uint32_t packh2(float lo, float hi) {
    uint32_t d;
    asm("cvt.rn.f16x2.f32 %0, %1, %2;" : "=r"(d) : "f"(hi), "f"(lo));
    return d;
}
__device__ __forceinline__ uint32_t ex2_h2(uint32_t t) {
    uint32_t d;
    asm("ex2.approx.f16x2 %0, %1;" : "=r"(d) : "r"(t));
    return d;
}

__device__ __forceinline__ void mma_f16(float& d0, float& d1, float& d2, float& d3,
                                        uint32_t a0, uint32_t a1, uint32_t a2, uint32_t a3,
                                        uint32_t b0, uint32_t b1) {
    asm volatile(
        "mma.sync.aligned.m16n8k16.row.col.f32.f16.f16.f32 "
        "{%0,%1,%2,%3}, {%4,%5,%6,%7}, {%8,%9}, {%0,%1,%2,%3};"
        : "+f"(d0), "+f"(d1), "+f"(d2), "+f"(d3)
        : "r"(a0), "r"(a1), "r"(a2), "r"(a3), "r"(b0), "r"(b1));
}

__device__ __forceinline__ uint32_t smem_u32(const void* p) {
    uint32_t a;
    asm("{ .reg .u64 t; cvta.to.shared.u64 t, %1; cvt.u32.u64 %0, t; }"
        : "=r"(a) : "l"(p));
    return a;
}
__device__ __forceinline__ void cp_async16(uint32_t dst, const void* src) {
    asm volatile("cp.async.cg.shared.global [%0], [%1], 16;"
                 :: "r"(dst), "l"(src) : "memory");
}
__device__ __forceinline__ void cp_commit() {
    asm volatile("cp.async.commit_group;" ::: "memory");
}
template <int N>
__device__ __forceinline__ void cp_wait() {
    asm volatile("cp.async.wait_group %0;" :: "n"(N) : "memory");
}

// ===========================================================================
// Convert inputs + weights to fp16 with pi-permuted contiguous (k) dimension.
// One thread per 16-element block.
// ===========================================================================
__global__ __launch_bounds__(256)
void cvt_kernel(const float* __restrict__ q, const float* __restrict__ k,
                const float* __restrict__ v,
                const float* __restrict__ wq, const float* __restrict__ wk,
                const float* __restrict__ wv, const float* __restrict__ wo,
                __half* __restrict__ inh, __half* __restrict__ wh)
{
    const int z = blockIdx.y;
    const int i = blockIdx.x * 256 + threadIdx.x;   // 16-element block index
    const float* src;
    __half* dst;
    int n;
    if (z < 3) {
        src = (z == 0) ? q : (z == 1) ? k : v;
        dst = inh + (size_t)z * M_ * H_;
        n = M_ * H_ / 16;
    } else {
        int w = z - 3;
        src = (w == 0) ? wq : (w == 1) ? wk : (w == 2) ? wv : wo;
        dst = wh + (size_t)w * H_ * H_;
        n = H_ * H_ / 16;
    }
    if (i >= n) return;
    const float4* s4 = (const float4*)(src + (size_t)i * 16);
    float4 f0 = s4[0], f1 = s4[1], f2 = s4[2], f3 = s4[3];
    uint4 lo, hi;
    lo.x = packh2(f0.x, f0.y);  lo.y = packh2(f2.x, f2.y);
    lo.z = packh2(f0.z, f0.w);  lo.w = packh2(f2.z, f2.w);
    hi.x = packh2(f1.x, f1.y);  hi.y = packh2(f3.x, f3.y);
    hi.z = packh2(f1.z, f1.w);  hi.w = packh2(f3.z, f3.w);
    uint4* d4 = (uint4*)(dst + (size_t)i * 16);
    d4[0] = lo;
    d4[1] = hi;
}

// ===========================================================================
// Fused mask: fm = (mask==0) ? -1 : script_mask * 0.125   (script_mask >= 0)
// ===========================================================================
__global__ __launch_bounds__(256)
void fuse_mask_kernel(const int* __restrict__ mask, const float* __restrict__ sm,
                      float* __restrict__ fm)
{
    int i = blockIdx.x * 256 + threadIdx.x;
    int4   m = ((const int4*)mask)[i];
    float4 s = ((const float4*)sm)[i];
    float4 o;
    o.x = (m.x == 0) ? -1.0f : s.x * 0.125f;
    o.y = (m.y == 0) ? -1.0f : s.y * 0.125f;
    o.z = (m.z == 0) ? -1.0f : s.z * 0.125f;
    o.w = (m.w == 0) ? -1.0f : s.w * 0.125f;
    ((float4*)fm)[i] = o;
}

// ===========================================================================
// fp16 GEMM core: acc = X @ W^T (both fp16, pi-permuted k). CTA 128x128,
// warp 64x32, K chunk 32, 3-stage cp.async, ONE barrier per chunk.
// pi makes fragment (k,k+8) pairs contiguous -> uint2 LDS.64 loads.
// ===========================================================================
#define RS 40
#define G_STAGE_HALVES (2 * 128 * RS)              // A + B, one stage = 10240
#define G_SMEM_BYTES   (3 * G_STAGE_HALVES * 2)    // 61440
#define G_NCHUNK (H_ / 32)                          // 32

struct GemmCtx {
    int warp_m, warp_n, qrow, qcol, m0, n0;
    float acc[16][4];
};

__device__ __forceinline__ void gemm_compute(
    GemmCtx& g, const __half* __restrict__ X, const __half* __restrict__ W)
{
    extern __shared__ __half gsh[];
    const uint32_t sb = smem_u32(gsh);

    const int tid  = threadIdx.x;
    const int wid  = tid >> 5;
    const int lane = tid & 31;
    g.m0 = blockIdx.y * 128;
    g.n0 = blockIdx.x * 128;
    g.warp_m = (wid & 1) * 64;
    g.warp_n = (wid >> 1) * 32;
    g.qrow = lane >> 2;
    g.qcol = lane & 3;

    const int r0 = tid >> 1;            // 0..127
    const int h0 = (tid & 1) * 16;      // half-offset base in row

    const __half* Xa = X + (size_t)(g.m0 + r0) * H_ + h0;
    const __half* Wb = W + (size_t)(g.n0 + r0) * H_ + h0;
    const uint32_t da = sb + (uint32_t)(r0 * RS + h0) * 2;
    const uint32_t db = da + (uint32_t)(128 * RS) * 2;

    auto issue = [&](int c) {
        const uint32_t so = (uint32_t)((c % 3) * G_STAGE_HALVES) * 2;
        const int k0 = c * 32;
        cp_async16(da + so,      Xa + k0);
        cp_async16(da + so + 16, Xa + k0 + 8);
        cp_async16(db + so,      Wb + k0);
        cp_async16(db + so + 16, Wb + k0 + 8);
        cp_commit();
    };

#pragma unroll
    for (int i = 0; i < 16; ++i)
#pragma unroll
        for (int j = 0; j < 4; ++j) g.acc[i][j] = 0.0f;

    issue(0);
    issue(1);

    for (int c = 0; c < G_NCHUNK; ++c) {
        cp_wait<1>();
        __syncthreads();
        if (c + 2 < G_NCHUNK) issue(c + 2);
        else cp_commit();

        const __half* As = gsh + (c % 3) * G_STAGE_HALVES;
        const __half* Bs = As + 128 * RS;

#pragma unroll
        for (int ks = 0; ks < 2; ++ks) {
            const int kk = ks * 16 + 4 * g.qcol;   // pi position of (2qc,2qc+1,2qc+8,2qc+9)
            uint32_t af[4][4];
            uint32_t bf[4][2];
#pragma unroll
            for (int mt = 0; mt < 4; ++mt) {
                const __half* ap = As + (g.warp_m + mt * 16 + g.qrow) * RS + kk;
                uint2 lo = *(const uint2*)ap;            // (a0, a2)
                uint2 hi = *(const uint2*)(ap + 8 * RS); // (a1, a3)
                af[mt][0] = lo.x; af[mt][1] = hi.x;
                af[mt][2] = lo.y; af[mt][3] = hi.y;
            }
#pragma unroll
            for (int nt = 0; nt < 4; ++nt) {
                const __half* bp = Bs + (g.warp_n + nt * 8 + g.qrow) * RS + kk;
                uint2 bb = *(const uint2*)bp;            // (b0, b1)
                bf[nt][0] = bb.x; bf[nt][1] = bb.y;
            }
#pragma unroll
            for (int mt = 0; mt < 4; ++mt)
#pragma unroll
                for (int nt = 0; nt < 4; ++nt)
                    mma_f16(g.acc[mt * 4 + nt][0], g.acc[mt * 4 + nt][1],
                            g.acc[mt * 4 + nt][2], g.acc[mt * 4 + nt][3],
                            af[mt][0], af[mt][1], af[mt][2], af[mt][3],
                            bf[nt][0], bf[nt][1]);
        }
    }
}

// Fused Q/K/V projections. z=0/1 -> fp16 [b][s][h] pi-store; z=2 -> fp16 V^T
// with pi-permuted s.
__global__ __launch_bounds__(256, 2)
void qkv_gemm_kernel(const __half* __restrict__ inh, const __half* __restrict__ wh,
                     const float* __restrict__ bq, const float* __restrict__ bk,
                     const float* __restrict__ bv,
                     __half* __restrict__ Cq, __half* __restrict__ Ck,
                     __half* __restrict__ Cvt)
{
    const int z = blockIdx.z;
    const __half* X = inh + (size_t)z * M_ * H_;
    const __half* W = wh + (size_t)z * H_ * H_;
    const float* bias = (z == 0) ? bq : (z == 1) ? bk : bv;

    GemmCtx g;
    gemm_compute(g, X, W);

    if (z < 2) {
        __half* C = (z == 0) ? Cq : Ck;
#pragma unroll
        for (int mt = 0; mt < 4; ++mt) {
            int row = g.m0 + g.warp_m + mt * 16 + g.qrow;
#pragma unroll
            for (int nt = 0; nt < 4; ++nt) {
                int col = g.n0 + g.warp_n + nt * 8 + 2 * g.qcol;      // old col
                // pi position: block base + 4qc + 2*(nt odd)
                int ncol = (col & ~15) + 4 * g.qcol + ((nt & 1) << 1);
                float b0v = __ldg(&bias[col]);
                float b1v = __ldg(&bias[col + 1]);
                uint32_t h0v = packh2(g.acc[mt * 4 + nt][0] + b0v,
                                      g.acc[mt * 4 + nt][1] + b1v);
                uint32_t h1v = packh2(g.acc[mt * 4 + nt][2] + b0v,
                                      g.acc[mt * 4 + nt][3] + b1v);
                *(uint32_t*)(C + (size_t)row * H_ + ncol)       = h0v;
                *(uint32_t*)(C + (size_t)(row + 8) * H_ + ncol) = h1v;
            }
        }
    } else {
        // V transposed: [b][h][hd][s], s pi-permuted within 16-blocks
#pragma unroll
        for (int mt = 0; mt < 4; ++mt) {
            int srow = g.m0 + g.warp_m + mt * 16 + g.qrow;
            int bb = srow >> 11, s = srow & 2047;
            int gr = s & 15;                     // = qrow (0..7)
            int pos0 = (s & ~15) + 4 * (gr >> 1) + (gr & 1);
#pragma unroll
            for (int nt = 0; nt < 4; ++nt) {
                int col = g.n0 + g.warp_n + nt * 8 + 2 * g.qcol;
                float b0v = __ldg(&bias[col]);
                float b1v = __ldg(&bias[col + 1]);
                int hh = col >> 6, hd = col & 63;
                __half* p = Cvt + ((size_t)(bb * NH_ + hh) * HD_ + hd) * S_;
                p[pos0]          = __float2half_rn(g.acc[mt * 4 + nt][0] + b0v);
                p[S_ + pos0]     = __float2half_rn(g.acc[mt * 4 + nt][1] + b1v);
                p[pos0 + 2]      = __float2half_rn(g.acc[mt * 4 + nt][2] + b0v);  // row s+8
                p[S_ + pos0 + 2] = __float2half_rn(g.acc[mt * 4 + nt][3] + b1v);
            }
        }
    }
}

__global__ __launch_bounds__(256, 2)
void out_gemm_kernel(const __half* __restrict__ X, const __half* __restrict__ wh,
                     const float* __restrict__ bias, float* __restrict__ C)
{
    GemmCtx g;
    gemm_compute(g, X, wh + (size_t)3 * H_ * H_);
#pragma unroll
    for (int mt = 0; mt < 4; ++mt) {
        int row = g.m0 + g.warp_m + mt * 16 + g.qrow;
#pragma unroll
        for (int nt = 0; nt < 4; ++nt) {
            int col = g.n0 + g.warp_n + nt * 8 + 2 * g.qcol;
            float b0v = __ldg(&bias[col]);
            float b1v = __ldg(&bias[col + 1]);
            *(float2*)(C + (size_t)row * H_ + col) =
                make_float2(g.acc[mt * 4 + nt][0] + b0v, g.acc[mt * 4 + nt][1] + b1v);
            *(float2*)(C + (size_t)(row + 8) * H_ + col) =
                make_float2(g.acc[mt * 4 + nt][2] + b0v, g.acc[mt * 4 + nt][3] + b1v);
        }
    }
}

// ===========================================================================
// fp16 mma flash attention. CTA: 128 Q rows, 8 warps x 16 rows. KV chunk 64,
// 2-stage cp.async, occ 2. Fixed-max softmax (M=4, no online max/rescale).
// pi-permuted K (hd) and Vt (s) -> uint2 fragment loads.
// ===========================================================================
#define KVC 64
#define NCH (S_ / KVC)          // 32
#define RSTH 72                 // smem row stride in halves
#define TILE_BYTES (64 * RSTH * 2)            // 9216
#define STG_BYTES  (2 * TILE_BYTES)           // 18432
#define ATT_SMEM_BYTES (2 * STG_BYTES)        // 36864

__global__ __launch_bounds__(256, 2)
void attn_mma_kernel(const __half* __restrict__ Qh, const __half* __restrict__ Kh,
                     const __half* __restrict__ Vth, const float* __restrict__ FM,
                     __half* __restrict__ Oh)
{
    extern __shared__ __half smh[];
    const uint32_t sb = smem_u32(smh);

    const int tid  = threadIdx.x;
    const int wid  = tid >> 5;
    const int lane = tid & 31;
    const int gr   = lane >> 2;    // 0..7
    const int qc   = lane & 3;     // 0..3
    const int q0   = blockIdx.x * 128;
    const int h    = blockIdx.y;
    const int b    = blockIdx.z;
    const int wrow = wid * 16;
    const float L2E = 1.44269504f;
    const float MB  = 4.0f * L2E;   // fixed softmax shift (log2 units)

    const size_t base   = (size_t)b * S_ * H_ + (size_t)h * HD_;
    const size_t vtbase = (size_t)(b * NH_ + h) * HD_ * S_;

    // Q fragments from pi-permuted Qh: uint2 at pi-pos ks*16+4qc
    uint32_t qf[4][4];
    {
        const __half* Qr0 = Qh + base + (size_t)(q0 + wrow + gr) * H_;
        const __half* Qr1 = Qh + base + (size_t)(q0 + wrow + gr + 8) * H_;
#pragma unroll
        for (int ks = 0; ks < 4; ++ks) {
            int c = ks * 16 + 4 * qc;
            uint2 lo = *(const uint2*)(Qr0 + c);
            uint2 hi = *(const uint2*)(Qr1 + c);
            qf[ks][0] = lo.x; qf[ks][1] = hi.x;
            qf[ks][2] = lo.y; qf[ks][3] = hi.y;
        }
    }

    float oacc[8][4];
#pragma unroll
    for (int i = 0; i < 8; ++i)
#pragma unroll
        for (int j = 0; j < 4; ++j) oacc[i][j] = 0.0f;
    float l_lo = 0.0f, l_hi = 0.0f;

    const int prow = tid >> 3;          // 0..31
    const int pch  = tid & 7;           // 0..7

    auto issue_chunk = [&](int c) {
        const int st = c & 1;
        const uint32_t kb = sb + st * STG_BYTES;
        const uint32_t vb = kb + TILE_BYTES;
        const int k0 = c * KVC;
#pragma unroll
        for (int it = 0; it < 2; ++it) {
            int r = prow + it * 32;     // 0..63
            cp_async16(kb + (uint32_t)(r * RSTH + pch * 8) * 2,
                       Kh + base + (size_t)(k0 + r) * H_ + pch * 8);
            cp_async16(vb + (uint32_t)(r * RSTH + pch * 8) * 2,
                       Vth + vtbase + (size_t)r * S_ + k0 + pch * 8);
        }
        cp_commit();
    };

    issue_chunk(0);

    const size_t fmbase_lo = ((size_t)b * S_ + (q0 + wrow + gr)) * S_;
    const size_t fmbase_hi = fmbase_lo + (size_t)8 * S_;

    for (int c = 0; c < NCH; ++c) {
        if (c > 0) __syncthreads();
        if (c + 1 < NCH) { issue_chunk(c + 1); cp_wait<1>(); }
        else             { cp_wait<0>(); }
        __syncthreads();

        const int st = c & 1;
        const __half* Ks = smh + st * (STG_BYTES / 2);
        const __half* Vs = Ks + TILE_BYTES / 2;
        const int k0 = c * KVC;

        // ---- S = Q K^T ----
        float sv[8][4];
#pragma unroll
        for (int i = 0; i < 8; ++i)
#pragma unroll
            for (int j = 0; j < 4; ++j) sv[i][j] = 0.0f;

#pragma unroll
        for (int ks = 0; ks < 4; ++ks) {
            const int kk = ks * 16 + 4 * qc;
#pragma unroll
            for (int nt = 0; nt < 8; ++nt) {
                const __half* bp = Ks + (nt * 8 + gr) * RSTH + kk;
                uint2 bb = *(const uint2*)bp;
                mma_f16(sv[nt][0], sv[nt][1], sv[nt][2], sv[nt][3],
                        qf[ks][0], qf[ks][1], qf[ks][2], qf[ks][3], bb.x, bb.y);
            }
        }

        // ---- mask + fixed-max exp (packed pairs ARE the PV A-fragments) ----
        uint32_t plo[8], phi[8];
        float rs_lo = 0.0f, rs_hi = 0.0f;
#pragma unroll
        for (int nt = 0; nt < 8; ++nt) {
            int colo = k0 + nt * 8 + 2 * qc;
            float2 fl = *(const float2*)&FM[fmbase_lo + colo];
            float2 fh = *(const float2*)&FM[fmbase_hi + colo];
            float t0 = (fl.x < 0.0f) ? -1e30f : fmaf(sv[nt][0] * fl.x, L2E, -MB);
            float t1 = (fl.y < 0.0f) ? -1e30f : fmaf(sv[nt][1] * fl.y, L2E, -MB);
            float t2 = (fh.x < 0.0f) ? -1e30f : fmaf(sv[nt][2] * fh.x, L2E, -MB);
            float t3 = (fh.y < 0.0f) ? -1e30f : fmaf(sv[nt][3] * fh.y, L2E, -MB);
            uint32_t pl = ex2_h2(packh2(t0, t1));
            uint32_t ph = ex2_h2(packh2(t2, t3));
            plo[nt] = pl; phi[nt] = ph;
            float2 f2l = __half22float2(*(const __half2*)&pl);
            float2 f2h = __half22float2(*(const __half2*)&ph);
            rs_lo += f2l.x + f2l.y;
            rs_hi += f2h.x + f2h.y;
        }
        l_lo += rs_lo;
        l_hi += rs_hi;

        // ---- O += P V : Vt pi-permuted s -> uint2 loads ----
#pragma unroll
        for (int t = 0; t < 4; ++t) {
            uint32_t a0 = plo[2 * t];
            uint32_t a1 = phi[2 * t];
            uint32_t a2 = plo[2 * t + 1];
            uint32_t a3 = phi[2 * t + 1];
            const int kk = t * 16 + 4 * qc;
#pragma unroll
            for (int nt = 0; nt < 8; ++nt) {
                const __half* vp = Vs + (nt * 8 + gr) * RSTH + kk;
                uint2 bb = *(const uint2*)vp;
                mma_f16(oacc[nt][0], oacc[nt][1], oacc[nt][2], oacc[nt][3],
                        a0, a1, a2, a3, bb.x, bb.y);
            }
        }
    }

    // ---- cross-lane l reduction + epilogue (pi-permuted AOh store) ----
    l_lo += __shfl_xor_sync(0xffffffffu, l_lo, 1);
    l_lo += __shfl_xor_sync(0xffffffffu, l_lo, 2);
    l_hi += __shfl_xor_sync(0xffffffffu, l_hi, 1);
    l_hi += __shfl_xor_sync(0xffffffffu, l_hi, 2);
    float inv_lo = 1.0f / l_lo;
    float inv_hi = 1.0f / l_hi;
    __half* Or0 = Oh + base + (size_t)(q0 + wrow + gr) * H_;
    __half* Or1 = Oh + base + (size_t)(q0 + wrow + gr + 8) * H_;
#pragma unroll
    for (int nt = 0; nt < 8; ++nt) {
        // old cols (nt*8+2qc, +1) -> pi pos within 16-block
        int ncol = ((nt & 6) << 3) + 4 * qc + ((nt & 1) << 1);
        *(uint32_t*)(Or0 + ncol) = packh2(oacc[nt][0] * inv_lo, oacc[nt][1] * inv_lo);
        *(uint32_t*)(Or1 + ncol) = packh2(oacc[nt][2] * inv_hi, oacc[nt][3] * inv_hi);
    }
}

// ---------------------------------------------------------------------------
extern "C" void kernel_launch(void* const* d_in, const int* in_sizes, int n_in,
                              void* d_out, int out_size)
{
    const float* query = (const float*)d_in[0];
    const float* key   = (const float*)d_in[1];
    const float* value = (const float*)d_in[2];
    const int*   mask  = (const int*)d_in[3];
    const float* smask = (const float*)d_in[4];
    const float* Wq = (const float*)d_in[5];
    const float* bq = (const float*)d_in[6];
    const float* Wk = (const float*)d_in[7];
    const float* bk = (const float*)d_in[8];
    const float* Wv = (const float*)d_in[9];
    const float* bv = (const float*)d_in[10];
    const float* Wo = (const float*)d_in[11];
    const float* bo = (const float*)d_in[12];
    float* out = (float*)d_out;

    __half *ginh, *gwh, *gqh, *gkh, *gvt, *gaoh;
    float *gfm;
    cudaGetSymbolAddress((void**)&ginh, g_INh);
    cudaGetSymbolAddress((void**)&gwh,  g_Wh);
    cudaGetSymbolAddress((void**)&gqh,  g_Qh);
    cudaGetSymbolAddress((void**)&gkh,  g_Kh);
    cudaGetSymbolAddress((void**)&gvt,  g_Vt);
    cudaGetSymbolAddress((void**)&gaoh, g_AOh);
    cudaGetSymbolAddress((void**)&gfm,  g_FM);

    cudaFuncSetAttribute(qkv_gemm_kernel,
                         cudaFuncAttributeMaxDynamicSharedMemorySize, G_SMEM_BYTES);
    cudaFuncSetAttribute(out_gemm_kernel,
                         cudaFuncAttributeMaxDynamicSharedMemorySize, G_SMEM_BYTES);
    cudaFuncSetAttribute(attn_mma_kernel,
                         cudaFuncAttributeMaxDynamicSharedMemorySize, ATT_SMEM_BYTES);

    dim3 cgrid(M_ * H_ / 16 / 256, 7);     // (1024, 7)
    cvt_kernel<<<cgrid, 256>>>(query, key, value, Wq, Wk, Wv, Wo, ginh, gwh);

    fuse_mask_kernel<<<(B_ * S_ * S_ / 4) / 256, 256>>>(mask, smask, gfm);

    dim3 gblk(256);
    dim3 qkvgrid(H_ / 128, M_ / 128, 3);   // (8, 32, 3)
    qkv_gemm_kernel<<<qkvgrid, gblk, G_SMEM_BYTES>>>(
        ginh, gwh, bq, bk, bv, gqh, gkh, gvt);

    dim3 agrid(S_ / 128, NH_, B_);         // (16, 16, 2)
    attn_mma_kernel<<<agrid, 256, ATT_SMEM_BYTES>>>(gqh, gkh, gvt, gfm, gaoh);

    dim3 ogrid(H_ / 128, M_ / 128);        // (8, 32)
    out_gemm_kernel<<<ogrid, gblk, G_SMEM_BYTES>>>(gaoh, gwh, bo, out);
}

// round 12
// speedup vs baseline: 1.0982x; 1.0982x over previous
#include <cuda_runtime.h>
#include <cuda_fp16.h>
#include <cstdint>
#include <cstddef>

#define B_  2
#define S_  2048
#define H_  1024
#define NH_ 16
#define HD_ 64
#define M_  (B_ * S_)   // 4096 rows

// Scratch (allocation-free rule: __device__ globals)
__device__ __align__(16) __half g_INh[(size_t)3 * M_ * H_];            // q,k,v inputs fp16
__device__ __align__(16) __half g_Wh[(size_t)4 * H_ * H_];             // Wq,Wk,Wv,Wo fp16
__device__ __align__(16) __half g_Qh[(size_t)M_ * H_];                 // [b][s][h] fp16
__device__ __align__(16) __half g_Kh[(size_t)M_ * H_];                 // [b][s][h] fp16
__device__ __align__(16) __half g_Vt[(size_t)B_ * NH_ * HD_ * S_];     // [b][h][hd][s] fp16
__device__ __align__(16) __half g_AOh[(size_t)M_ * H_];                // attn out fp16
__device__ __align__(16) __half g_FMh[(size_t)B_ * S_ * S_];           // -1 or sm*0.125 (fp16)

// ---------------------------------------------------------------------------
__device__ __forceinline__ uint32_t packh2(float lo, float hi) {
    uint32_t d;   // cvt.rn.f16x2.f32 d, a, b  ->  d.hi = a, d.lo = b
    asm("cvt.rn.f16x2.f32 %0, %1, %2;" : "=r"(d) : "f"(hi), "f"(lo));
    return d;
}
__device__ __forceinline__ uint32_t ex2_h2(uint32_t t) {
    uint32_t d;
    asm("ex2.approx.f16x2 %0, %1;" : "=r"(d) : "r"(t));
    return d;
}

__device__ __forceinline__ void mma_f16(float& d0, float& d1, float& d2, float& d3,
                                        uint32_t a0, uint32_t a1, uint32_t a2, uint32_t a3,
                                        uint32_t b0, uint32_t b1) {
    asm volatile(
        "mma.sync.aligned.m16n8k16.row.col.f32.f16.f16.f32 "
        "{%0,%1,%2,%3}, {%4,%5,%6,%7}, {%8,%9}, {%0,%1,%2,%3};"
        : "+f"(d0), "+f"(d1), "+f"(d2), "+f"(d3)
        : "r"(a0), "r"(a1), "r"(a2), "r"(a3), "r"(b0), "r"(b1));
}

__device__ __forceinline__ uint32_t smem_u32(const void* p) {
    uint32_t a;
    asm("{ .reg .u64 t; cvta.to.shared.u64 t, %1; cvt.u32.u64 %0, t; }"
        : "=r"(a) : "l"(p));
    return a;
}
__device__ __forceinline__ void cp_async16(uint32_t dst, const void* src) {
    asm volatile("cp.async.cg.shared.global [%0], [%1], 16;"
                 :: "r"(dst), "l"(src) : "memory");
}
__device__ __forceinline__ void cp_commit() {
    asm volatile("cp.async.commit_group;" ::: "memory");
}
template <int N>
__device__ __forceinline__ void cp_wait() {
    asm volatile("cp.async.wait_group %0;" :: "n"(N) : "memory");
}

// ===========================================================================
// Convert inputs + weights to fp16 (once). z<3: q/k/v (M_*H_); z>=3: W (H_*H_)
// ===========================================================================
__global__ __launch_bounds__(256)
void cvt_kernel(const float* __restrict__ q, const float* __restrict__ k,
                const float* __restrict__ v,
                const float* __restrict__ wq, const float* __restrict__ wk,
                const float* __restrict__ wv, const float* __restrict__ wo,
                __half* __restrict__ inh, __half* __restrict__ wh)
{
    const int z = blockIdx.y;
    const int i = blockIdx.x * 256 + threadIdx.x;   // float4 index
    const float* src;
    __half* dst;
    int n;
    if (z < 3) {
        src = (z == 0) ? q : (z == 1) ? k : v;
        dst = inh + (size_t)z * M_ * H_;
        n = M_ * H_ / 4;
    } else {
        int w = z - 3;
        src = (w == 0) ? wq : (w == 1) ? wk : (w == 2) ? wv : wo;
        dst = wh + (size_t)w * H_ * H_;
        n = H_ * H_ / 4;
    }
    if (i < n) {
        float4 f = ((const float4*)src)[i];
        uint2 o;
        o.x = packh2(f.x, f.y);
        o.y = packh2(f.z, f.w);
        ((uint2*)dst)[i] = o;
    }
}

// ===========================================================================
// Fused mask (fp16): fm = (mask==0) ? -1 : script_mask * 0.125
// ===========================================================================
__global__ __launch_bounds__(256)
void fuse_mask_kernel(const int* __restrict__ mask, const float* __restrict__ sm,
                      __half* __restrict__ fm)
{
    int i = blockIdx.x * 256 + threadIdx.x;
    int4   m = ((const int4*)mask)[i];
    float4 s = ((const float4*)sm)[i];
    float o0 = (m.x == 0) ? -1.0f : s.x * 0.125f;
    float o1 = (m.y == 0) ? -1.0f : s.y * 0.125f;
    float o2 = (m.z == 0) ? -1.0f : s.z * 0.125f;
    float o3 = (m.w == 0) ? -1.0f : s.w * 0.125f;
    uint2 o;
    o.x = packh2(o0, o1);
    o.y = packh2(o2, o3);
    ((uint2*)fm)[i] = o;
}

// ===========================================================================
// fp16 GEMM core (R10-proven): acc = X @ W^T. CTA 128x128, warp 64x32,
// K chunk 32, 3-stage cp.async, ONE barrier per chunk, fp16 smem, RS=40.
// ===========================================================================
#define RS 40
#define G_STAGE_HALVES (2 * 128 * RS)              // A + B, one stage = 10240
#define G_SMEM_BYTES   (3 * G_STAGE_HALVES * 2)    // 61440
#define G_NCHUNK (H_ / 32)                          // 32

struct GemmCtx {
    int warp_m, warp_n, qrow, qcol, m0, n0;
    float acc[16][4];
};

__device__ __forceinline__ void gemm_compute(
    GemmCtx& g, const __half* __restrict__ X, const __half* __restrict__ W)
{
    extern __shared__ __half gsh[];
    const uint32_t sb = smem_u32(gsh);

    const int tid  = threadIdx.x;
    const int wid  = tid >> 5;
    const int lane = tid & 31;
    g.m0 = blockIdx.y * 128;
    g.n0 = blockIdx.x * 128;
    g.warp_m = (wid & 1) * 64;
    g.warp_n = (wid >> 1) * 32;
    g.qrow = lane >> 2;
    g.qcol = lane & 3;

    const int r0 = tid >> 1;            // 0..127
    const int h0 = (tid & 1) * 16;      // half-offset base in row

    const __half* Xa = X + (size_t)(g.m0 + r0) * H_ + h0;
    const __half* Wb = W + (size_t)(g.n0 + r0) * H_ + h0;
    const uint32_t da = sb + (uint32_t)(r0 * RS + h0) * 2;
    const uint32_t db = da + (uint32_t)(128 * RS) * 2;

    auto issue = [&](int c) {
        const uint32_t so = (uint32_t)((c % 3) * G_STAGE_HALVES) * 2;
        const int k0 = c * 32;
        cp_async16(da + so,      Xa + k0);
        cp_async16(da + so + 16, Xa + k0 + 8);
        cp_async16(db + so,      Wb + k0);
        cp_async16(db + so + 16, Wb + k0 + 8);
        cp_commit();
    };

#pragma unroll
    for (int i = 0; i < 16; ++i)
#pragma unroll
        for (int j = 0; j < 4; ++j) g.acc[i][j] = 0.0f;

    issue(0);
    issue(1);

    for (int c = 0; c < G_NCHUNK; ++c) {
        cp_wait<1>();          // group c complete (groups retire in order)
        __syncthreads();       // data visible + all warps finished chunk c-1
        if (c + 2 < G_NCHUNK) issue(c + 2);   // writes stage (c-1)%3: safe
        else cp_commit();                      // keep group-count invariant

        const __half* As = gsh + (c % 3) * G_STAGE_HALVES;
        const __half* Bs = As + 128 * RS;

#pragma unroll
        for (int ks = 0; ks < 2; ++ks) {
            const int kk = ks * 16 + 2 * g.qcol;
            uint32_t af[4][4];
            uint32_t bf[4][2];
#pragma unroll
            for (int mt = 0; mt < 4; ++mt) {
                const __half* ap = As + (g.warp_m + mt * 16 + g.qrow) * RS + kk;
                af[mt][0] = *(const uint32_t*)ap;
                af[mt][1] = *(const uint32_t*)(ap + 8 * RS);
                af[mt][2] = *(const uint32_t*)(ap + 8);
                af[mt][3] = *(const uint32_t*)(ap + 8 * RS + 8);
            }
#pragma unroll
            for (int nt = 0; nt < 4; ++nt) {
                const __half* bp = Bs + (g.warp_n + nt * 8 + g.qrow) * RS + kk;
                bf[nt][0] = *(const uint32_t*)bp;
                bf[nt][1] = *(const uint32_t*)(bp + 8);
            }
#pragma unroll
            for (int mt = 0; mt < 4; ++mt)
#pragma unroll
                for (int nt = 0; nt < 4; ++nt)
                    mma_f16(g.acc[mt * 4 + nt][0], g.acc[mt * 4 + nt][1],
                            g.acc[mt * 4 + nt][2], g.acc[mt * 4 + nt][3],
                            af[mt][0], af[mt][1], af[mt][2], af[mt][3],
                            bf[nt][0], bf[nt][1]);
        }
    }
}

// Fused Q/K/V projections. z=0/1 -> fp16 [b][s][h] store; z=2 -> fp16 V^T store.
__global__ __launch_bounds__(256, 2)
void qkv_gemm_kernel(const __half* __restrict__ inh, const __half* __restrict__ wh,
                     const float* __restrict__ bq, const float* __restrict__ bk,
                     const float* __restrict__ bv,
                     __half* __restrict__ Cq, __half* __restrict__ Ck,
                     __half* __restrict__ Cvt)
{
    const int z = blockIdx.z;
    const __half* X = inh + (size_t)z * M_ * H_;
    const __half* W = wh + (size_t)z * H_ * H_;
    const float* bias = (z == 0) ? bq : (z == 1) ? bk : bv;

    GemmCtx g;
    gemm_compute(g, X, W);

    if (z < 2) {
        __half* C = (z == 0) ? Cq : Ck;
#pragma unroll
        for (int mt = 0; mt < 4; ++mt) {
            int row = g.m0 + g.warp_m + mt * 16 + g.qrow;
#pragma unroll
            for (int nt = 0; nt < 4; ++nt) {
                int col = g.n0 + g.warp_n + nt * 8 + 2 * g.qcol;
                float b0v = __ldg(&bias[col]);
                float b1v = __ldg(&bias[col + 1]);
                uint32_t h0v = packh2(g.acc[mt * 4 + nt][0] + b0v,
                                      g.acc[mt * 4 + nt][1] + b1v);
                uint32_t h1v = packh2(g.acc[mt * 4 + nt][2] + b0v,
                                      g.acc[mt * 4 + nt][3] + b1v);
                *(uint32_t*)(C + (size_t)row * H_ + col)       = h0v;
                *(uint32_t*)(C + (size_t)(row + 8) * H_ + col) = h1v;
            }
        }
    } else {
        // V transposed: [b][h][hd][s]
#pragma unroll
        for (int mt = 0; mt < 4; ++mt) {
            int srow = g.m0 + g.warp_m + mt * 16 + g.qrow;
            int bb = srow >> 11, s = srow & 2047;
#pragma unroll
            for (int nt = 0; nt < 4; ++nt) {
                int col = g.n0 + g.warp_n + nt * 8 + 2 * g.qcol;
                float b0v = __ldg(&bias[col]);
                float b1v = __ldg(&bias[col + 1]);
                int hh = col >> 6, hd = col & 63;
                __half* p = Cvt + ((size_t)(bb * NH_ + hh) * HD_ + hd) * S_;
                p[s]          = __float2half_rn(g.acc[mt * 4 + nt][0] + b0v);
                p[S_ + s]     = __float2half_rn(g.acc[mt * 4 + nt][1] + b1v);
                p[s + 8]      = __float2half_rn(g.acc[mt * 4 + nt][2] + b0v);
                p[S_ + s + 8] = __float2half_rn(g.acc[mt * 4 + nt][3] + b1v);
            }
        }
    }
}

__global__ __launch_bounds__(256, 2)
void out_gemm_kernel(const __half* __restrict__ X, const __half* __restrict__ wh,
                     const float* __restrict__ bias, float* __restrict__ C)
{
    GemmCtx g;
    gemm_compute(g, X, wh + (size_t)3 * H_ * H_);
#pragma unroll
    for (int mt = 0; mt < 4; ++mt) {
        int row = g.m0 + g.warp_m + mt * 16 + g.qrow;
#pragma unroll
        for (int nt = 0; nt < 4; ++nt) {
            int col = g.n0 + g.warp_n + nt * 8 + 2 * g.qcol;
            float b0v = __ldg(&bias[col]);
            float b1v = __ldg(&bias[col + 1]);
            *(float2*)(C + (size_t)row * H_ + col) =
                make_float2(g.acc[mt * 4 + nt][0] + b0v, g.acc[mt * 4 + nt][1] + b1v);
            *(float2*)(C + (size_t)(row + 8) * H_ + col) =
                make_float2(g.acc[mt * 4 + nt][2] + b0v, g.acc[mt * 4 + nt][3] + b1v);
        }
    }
}

// ===========================================================================
// fp16 mma flash attention (R10-proven core). CTA: 128 Q rows, 8 warps.
// KV chunk 64, 2-stage cp.async, occ 2. ex2.f16x2 softmax with online max.
// Deltas vs R10: fp16 FM via __ldcs; lane-local l accumulation (end reduce).
// ===========================================================================
#define KVC 64
#define NCH (S_ / KVC)          // 32
#define RSTH 72                 // smem row stride in halves (64 data + 8 pad)
#define TILE_BYTES (64 * RSTH * 2)            // 9216
#define STG_BYTES  (2 * TILE_BYTES)           // K + Vt, one stage = 18432
#define ATT_SMEM_BYTES (2 * STG_BYTES)        // 36864

__global__ __launch_bounds__(256, 2)
void attn_mma_kernel(const __half* __restrict__ Qh, const __half* __restrict__ Kh,
                     const __half* __restrict__ Vth, const __half* __restrict__ FMh,
                     __half* __restrict__ Oh)
{
    extern __shared__ __half smh[];
    const uint32_t sb = smem_u32(smh);

    const int tid  = threadIdx.x;
    const int wid  = tid >> 5;
    const int lane = tid & 31;
    const int gr   = lane >> 2;    // 0..7
    const int qc   = lane & 3;     // 0..3
    const int q0   = blockIdx.x * 128;
    const int h    = blockIdx.y;
    const int b    = blockIdx.z;
    const int wrow = wid * 16;
    const float L2E = 1.44269504f;

    const size_t base   = (size_t)b * S_ * H_ + (size_t)h * HD_;       // Q/K halves
    const size_t vtbase = (size_t)(b * NH_ + h) * HD_ * S_;            // Vt halves

    uint32_t qf[4][4];
    {
        const __half* Qr0 = Qh + base + (size_t)(q0 + wrow + gr) * H_;
        const __half* Qr1 = Qh + base + (size_t)(q0 + wrow + gr + 8) * H_;
#pragma unroll
        for (int ks = 0; ks < 4; ++ks) {
            int c = ks * 16 + 2 * qc;
            qf[ks][0] = *(const uint32_t*)(Qr0 + c);
            qf[ks][1] = *(const uint32_t*)(Qr1 + c);
            qf[ks][2] = *(const uint32_t*)(Qr0 + c + 8);
            qf[ks][3] = *(const uint32_t*)(Qr1 + c + 8);
        }
    }

    float oacc[8][4];
#pragma unroll
    for (int i = 0; i < 8; ++i)
#pragma unroll
        for (int j = 0; j < 4; ++j) oacc[i][j] = 0.0f;
    float m_lo = -1e30f, m_hi = -1e30f, l_lo = 0.0f, l_hi = 0.0f;   // l is lane-local

    const int prow = tid >> 3;          // 0..31
    const int pch  = tid & 7;           // 0..7

    auto issue_chunk = [&](int c) {
        const int st = c & 1;
        const uint32_t kb = sb + st * STG_BYTES;
        const uint32_t vb = kb + TILE_BYTES;
        const int k0 = c * KVC;
#pragma unroll
        for (int it = 0; it < 2; ++it) {
            int r = prow + it * 32;     // 0..63
            cp_async16(kb + (uint32_t)(r * RSTH + pch * 8) * 2,
                       Kh + base + (size_t)(k0 + r) * H_ + pch * 8);
            cp_async16(vb + (uint32_t)(r * RSTH + pch * 8) * 2,
                       Vth + vtbase + (size_t)r * S_ + k0 + pch * 8);
        }
        cp_commit();
    };

    issue_chunk(0);

    const size_t fmbase_lo = ((size_t)b * S_ + (q0 + wrow + gr)) * S_;
    const size_t fmbase_hi = fmbase_lo + (size_t)8 * S_;

    for (int c = 0; c < NCH; ++c) {
        if (c > 0) __syncthreads();
        if (c + 1 < NCH) { issue_chunk(c + 1); cp_wait<1>(); }
        else             { cp_wait<0>(); }
        __syncthreads();

        const int st = c & 1;
        const __half* Ks = smh + st * (STG_BYTES / 2);
        const __half* Vs = Ks + TILE_BYTES / 2;
        const int k0 = c * KVC;

        // ---- S = Q K^T ----
        float sv[8][4];
#pragma unroll
        for (int i = 0; i < 8; ++i)
#pragma unroll
            for (int j = 0; j < 4; ++j) sv[i][j] = 0.0f;

#pragma unroll
        for (int ks = 0; ks < 4; ++ks) {
            const int kk = ks * 16 + 2 * qc;
#pragma unroll
            for (int nt = 0; nt < 8; ++nt) {
                const __half* bp = Ks + (nt * 8 + gr) * RSTH + kk;
                uint32_t b0 = *(const uint32_t*)bp;
                uint32_t b1 = *(const uint32_t*)(bp + 8);
                mma_f16(sv[nt][0], sv[nt][1], sv[nt][2], sv[nt][3],
                        qf[ks][0], qf[ks][1], qf[ks][2], qf[ks][3], b0, b1);
            }
        }

        // ---- fused mask (fp16, streaming) + row max ----
        float tmax_lo = -1e30f, tmax_hi = -1e30f;
#pragma unroll
        for (int nt = 0; nt < 8; ++nt) {
            int colo = k0 + nt * 8 + 2 * qc;
            uint32_t ul = __ldcs((const uint32_t*)(FMh + fmbase_lo + colo));
            uint32_t uh = __ldcs((const uint32_t*)(FMh + fmbase_hi + colo));
            float2 fl = __half22float2(*(const __half2*)&ul);
            float2 fh = __half22float2(*(const __half2*)&uh);
            float s0 = (fl.x < 0.0f) ? -1e30f : sv[nt][0] * fl.x;
            float s1 = (fl.y < 0.0f) ? -1e30f : sv[nt][1] * fl.y;
            float s2 = (fh.x < 0.0f) ? -1e30f : sv[nt][2] * fh.x;
            float s3 = (fh.y < 0.0f) ? -1e30f : sv[nt][3] * fh.y;
            sv[nt][0] = s0; sv[nt][1] = s1; sv[nt][2] = s2; sv[nt][3] = s3;
            tmax_lo = fmaxf(tmax_lo, fmaxf(s0, s1));
            tmax_hi = fmaxf(tmax_hi, fmaxf(s2, s3));
        }
        tmax_lo = fmaxf(tmax_lo, __shfl_xor_sync(0xffffffffu, tmax_lo, 1));
        tmax_lo = fmaxf(tmax_lo, __shfl_xor_sync(0xffffffffu, tmax_lo, 2));
        tmax_hi = fmaxf(tmax_hi, __shfl_xor_sync(0xffffffffu, tmax_hi, 1));
        tmax_hi = fmaxf(tmax_hi, __shfl_xor_sync(0xffffffffu, tmax_hi, 2));

        float newm_lo = fmaxf(m_lo, tmax_lo);
        float newm_hi = fmaxf(m_hi, tmax_hi);
        float alpha_lo = __expf(m_lo - newm_lo);
        float alpha_hi = __expf(m_hi - newm_hi);
        m_lo = newm_lo; m_hi = newm_hi;

        // ---- exp via ex2.f16x2; lane-local l accumulation (no shfl here) ----
        const float ml_lo = newm_lo * L2E;
        const float ml_hi = newm_hi * L2E;
        uint32_t plo[8], phi[8];
        float rs_lo = 0.0f, rs_hi = 0.0f;
#pragma unroll
        for (int nt = 0; nt < 8; ++nt) {
            float t0 = fmaf(sv[nt][0], L2E, -ml_lo);
            float t1 = fmaf(sv[nt][1], L2E, -ml_lo);
            float t2 = fmaf(sv[nt][2], L2E, -ml_hi);
            float t3 = fmaf(sv[nt][3], L2E, -ml_hi);
            uint32_t pl = ex2_h2(packh2(t0, t1));
            uint32_t ph = ex2_h2(packh2(t2, t3));
            plo[nt] = pl; phi[nt] = ph;
            float2 f2l = __half22float2(*(const __half2*)&pl);
            float2 f2h = __half22float2(*(const __half2*)&ph);
            rs_lo += f2l.x + f2l.y;
            rs_hi += f2h.x + f2h.y;
        }
        l_lo = l_lo * alpha_lo + rs_lo;
        l_hi = l_hi * alpha_hi + rs_hi;

        // ---- rescale O ----
#pragma unroll
        for (int nt = 0; nt < 8; ++nt) {
            oacc[nt][0] *= alpha_lo; oacc[nt][1] *= alpha_lo;
            oacc[nt][2] *= alpha_hi; oacc[nt][3] *= alpha_hi;
        }

        // ---- O += P V : packed P pairs map directly onto A-fragments ----
#pragma unroll
        for (int t = 0; t < 4; ++t) {
            uint32_t a0 = plo[2 * t];
            uint32_t a1 = phi[2 * t];
            uint32_t a2 = plo[2 * t + 1];
            uint32_t a3 = phi[2 * t + 1];
            const int kk = t * 16 + 2 * qc;
#pragma unroll
            for (int nt = 0; nt < 8; ++nt) {
                const __half* vp = Vs + (nt * 8 + gr) * RSTH + kk;
                uint32_t b0 = *(const uint32_t*)vp;
                uint32_t b1 = *(const uint32_t*)(vp + 8);
                mma_f16(oacc[nt][0], oacc[nt][1], oacc[nt][2], oacc[nt][3],
                        a0, a1, a2, a3, b0, b1);
            }
        }
    }

    // ---- final l reduction + epilogue: fp16 AO ----
    l_lo += __shfl_xor_sync(0xffffffffu, l_lo, 1);
    l_lo += __shfl_xor_sync(0xffffffffu, l_lo, 2);
    l_hi += __shfl_xor_sync(0xffffffffu, l_hi, 1);
    l_hi += __shfl_xor_sync(0xffffffffu, l_hi, 2);
    float inv_lo = 1.0f / l_lo;
    float inv_hi = 1.0f / l_hi;
    __half* Or0 = Oh + base + (size_t)(q0 + wrow + gr) * H_;
    __half* Or1 = Oh + base + (size_t)(q0 + wrow + gr + 8) * H_;
#pragma unroll
    for (int nt = 0; nt < 8; ++nt) {
        int col = nt * 8 + 2 * qc;
        *(uint32_t*)(Or0 + col) = packh2(oacc[nt][0] * inv_lo, oacc[nt][1] * inv_lo);
        *(uint32_t*)(Or1 + col) = packh2(oacc[nt][2] * inv_hi, oacc[nt][3] * inv_hi);
    }
}

// ---------------------------------------------------------------------------
extern "C" void kernel_launch(void* const* d_in, const int* in_sizes, int n_in,
                              void* d_out, int out_size)
{
    const float* query = (const float*)d_in[0];
    const float* key   = (const float*)d_in[1];
    const float* value = (const float*)d_in[2];
    const int*   mask  = (const int*)d_in[3];
    const float* smask = (const float*)d_in[4];
    const float* Wq = (const float*)d_in[5];
    const float* bq = (const float*)d_in[6];
    const float* Wk = (const float*)d_in[7];
    const float* bk = (const float*)d_in[8];
    const float* Wv = (const float*)d_in[9];
    const float* bv = (const float*)d_in[10];
    const float* Wo = (const float*)d_in[11];
    const float* bo = (const float*)d_in[12];
    float* out = (float*)d_out;

    __half *ginh, *gwh, *gqh, *gkh, *gvt, *gaoh, *gfmh;
    cudaGetSymbolAddress((void**)&ginh, g_INh);
    cudaGetSymbolAddress((void**)&gwh,  g_Wh);
    cudaGetSymbolAddress((void**)&gqh,  g_Qh);
    cudaGetSymbolAddress((void**)&gkh,  g_Kh);
    cudaGetSymbolAddress((void**)&gvt,  g_Vt);
    cudaGetSymbolAddress((void**)&gaoh, g_AOh);
    cudaGetSymbolAddress((void**)&gfmh, g_FMh);

    cudaFuncSetAttribute(qkv_gemm_kernel,
                         cudaFuncAttributeMaxDynamicSharedMemorySize, G_SMEM_BYTES);
    cudaFuncSetAttribute(out_gemm_kernel,
                         cudaFuncAttributeMaxDynamicSharedMemorySize, G_SMEM_BYTES);
    cudaFuncSetAttribute(attn_mma_kernel,
                         cudaFuncAttributeMaxDynamicSharedMemorySize, ATT_SMEM_BYTES);

    dim3 cgrid(M_ * H_ / 4 / 256, 7);      // (4096, 7)
    cvt_kernel<<<cgrid, 256>>>(query, key, value, Wq, Wk, Wv, Wo, ginh, gwh);

    fuse_mask_kernel<<<(B_ * S_ * S_ / 4) / 256, 256>>>(mask, smask, gfmh);

    dim3 gblk(256);
    dim3 qkvgrid(H_ / 128, M_ / 128, 3);   // (8, 32, 3)
    qkv_gemm_kernel<<<qkvgrid, gblk, G_SMEM_BYTES>>>(
        ginh, gwh, bq, bk, bv, gqh, gkh, gvt);

    dim3 agrid(S_ / 128, NH_, B_);         // (16, 16, 2)
    attn_mma_kernel<<<agrid, 256, ATT_SMEM_BYTES>>>(gqh, gkh, gvt, gfmh, gaoh);

    dim3 ogrid(H_ / 128, M_ / 128);        // (8, 32)
    out_gemm_kernel<<<ogrid, gblk, G_SMEM_BYTES>>>(gaoh, gwh, bo, out);
}

// round 13
// speedup vs baseline: 1.1832x; 1.0775x over previous
#include <cuda_runtime.h>
#include <cuda_fp16.h>
#include <cstdint>
#include <cstddef>

#define B_  2
#define S_  2048
#define H_  1024
#define NH_ 16
#define HD_ 64
#define M_  (B_ * S_)   // 4096 rows

// Scratch (allocation-free rule: __device__ globals)
// Qh/Kh: hd-dim pi-permuted within 16-blocks (old pair (2q,2q+1)->pos 4q,
// old pair (2q+8,2q+9)->pos 4q+2). Vt: s-dim pi-permuted the same way.
__device__ __align__(16) __half g_INh[(size_t)3 * M_ * H_];            // q,k,v inputs fp16
__device__ __align__(16) __half g_Wh[(size_t)4 * H_ * H_];             // Wq,Wk,Wv,Wo fp16
__device__ __align__(16) __half g_Qh[(size_t)M_ * H_];                 // [b][s][h] fp16 (hd pi)
__device__ __align__(16) __half g_Kh[(size_t)M_ * H_];                 // [b][s][h] fp16 (hd pi)
__device__ __align__(16) __half g_Vt[(size_t)B_ * NH_ * HD_ * S_];     // [b][h][hd][s] fp16 (s pi)
__device__ __align__(16) __half g_AOh[(size_t)M_ * H_];                // attn out fp16 (natural)
__device__ __align__(16) __half g_FMh[(size_t)B_ * S_ * S_];           // -1 or sm*0.125 (fp16)

// ---------------------------------------------------------------------------
__device__ __forceinline__ uint32_t packh2(float lo, float hi) {
    uint32_t d;
    asm("cvt.rn.f16x2.f32 %0, %1, %2;" : "=r"(d) : "f"(hi), "f"(lo));
    return d;
}
__device__ __forceinline__ uint32_t ex2_h2(uint32_t t) {
    uint32_t d;
    asm("ex2.approx.f16x2 %0, %1;" : "=r"(d) : "r"(t));
    return d;
}

__device__ __forceinline__ void mma_f16(float& d0, float& d1, float& d2, float& d3,
                                        uint32_t a0, uint32_t a1, uint32_t a2, uint32_t a3,
                                        uint32_t b0, uint32_t b1) {
    asm volatile(
        "mma.sync.aligned.m16n8k16.row.col.f32.f16.f16.f32 "
        "{%0,%1,%2,%3}, {%4,%5,%6,%7}, {%8,%9}, {%0,%1,%2,%3};"
        : "+f"(d0), "+f"(d1), "+f"(d2), "+f"(d3)
        : "r"(a0), "r"(a1), "r"(a2), "r"(a3), "r"(b0), "r"(b1));
}

__device__ __forceinline__ uint32_t smem_u32(const void* p) {
    uint32_t a;
    asm("{ .reg .u64 t; cvta.to.shared.u64 t, %1; cvt.u32.u64 %0, t; }"
        : "=r"(a) : "l"(p));
    return a;
}
__device__ __forceinline__ void cp_async16(uint32_t dst, const void* src) {
    asm volatile("cp.async.cg.shared.global [%0], [%1], 16;"
                 :: "r"(dst), "l"(src) : "memory");
}
__device__ __forceinline__ void cp_commit() {
    asm volatile("cp.async.commit_group;" ::: "memory");
}
template <int N>
__device__ __forceinline__ void cp_wait() {
    asm volatile("cp.async.wait_group %0;" :: "n"(N) : "memory");
}

// ===========================================================================
// Convert inputs + weights to fp16 (once). Natural order (GEMM is un-pi'd).
// ===========================================================================
__global__ __launch_bounds__(256)
void cvt_kernel(const float* __restrict__ q, const float* __restrict__ k,
                const float* __restrict__ v,
                const float* __restrict__ wq, const float* __restrict__ wk,
                const float* __restrict__ wv, const float* __restrict__ wo,
                __half* __restrict__ inh, __half* __restrict__ wh)
{
    const int z = blockIdx.y;
    const int i = blockIdx.x * 256 + threadIdx.x;   // float4 index
    const float* src;
    __half* dst;
    int n;
    if (z < 3) {
        src = (z == 0) ? q : (z == 1) ? k : v;
        dst = inh + (size_t)z * M_ * H_;
        n = M_ * H_ / 4;
    } else {
        int w = z - 3;
        src = (w == 0) ? wq : (w == 1) ? wk : (w == 2) ? wv : wo;
        dst = wh + (size_t)w * H_ * H_;
        n = H_ * H_ / 4;
    }
    if (i < n) {
        float4 f = ((const float4*)src)[i];
        uint2 o;
        o.x = packh2(f.x, f.y);
        o.y = packh2(f.z, f.w);
        ((uint2*)dst)[i] = o;
    }
}

// ===========================================================================
// Fused mask (fp16): fm = (mask==0) ? -1 : script_mask * 0.125
// ===========================================================================
__global__ __launch_bounds__(256)
void fuse_mask_kernel(const int* __restrict__ mask, const float* __restrict__ sm,
                      __half* __restrict__ fm)
{
    int i = blockIdx.x * 256 + threadIdx.x;
    int4   m = ((const int4*)mask)[i];
    float4 s = ((const float4*)sm)[i];
    float o0 = (m.x == 0) ? -1.0f : s.x * 0.125f;
    float o1 = (m.y == 0) ? -1.0f : s.y * 0.125f;
    float o2 = (m.z == 0) ? -1.0f : s.z * 0.125f;
    float o3 = (m.w == 0) ? -1.0f : s.w * 0.125f;
    uint2 o;
    o.x = packh2(o0, o1);
    o.y = packh2(o2, o3);
    ((uint2*)fm)[i] = o;
}

// ===========================================================================
// fp16 GEMM core (R10-proven, unchanged): acc = X @ W^T. CTA 128x128,
// warp 64x32, K chunk 32, 3-stage cp.async, ONE barrier per chunk, RS=40.
// ===========================================================================
#define RS 40
#define G_STAGE_HALVES (2 * 128 * RS)              // A + B, one stage = 10240
#define G_SMEM_BYTES   (3 * G_STAGE_HALVES * 2)    // 61440
#define G_NCHUNK (H_ / 32)                          // 32

struct GemmCtx {
    int warp_m, warp_n, qrow, qcol, m0, n0;
    float acc[16][4];
};

__device__ __forceinline__ void gemm_compute(
    GemmCtx& g, const __half* __restrict__ X, const __half* __restrict__ W)
{
    extern __shared__ __half gsh[];
    const uint32_t sb = smem_u32(gsh);

    const int tid  = threadIdx.x;
    const int wid  = tid >> 5;
    const int lane = tid & 31;
    g.m0 = blockIdx.y * 128;
    g.n0 = blockIdx.x * 128;
    g.warp_m = (wid & 1) * 64;
    g.warp_n = (wid >> 1) * 32;
    g.qrow = lane >> 2;
    g.qcol = lane & 3;

    const int r0 = tid >> 1;            // 0..127
    const int h0 = (tid & 1) * 16;      // half-offset base in row

    const __half* Xa = X + (size_t)(g.m0 + r0) * H_ + h0;
    const __half* Wb = W + (size_t)(g.n0 + r0) * H_ + h0;
    const uint32_t da = sb + (uint32_t)(r0 * RS + h0) * 2;
    const uint32_t db = da + (uint32_t)(128 * RS) * 2;

    auto issue = [&](int c) {
        const uint32_t so = (uint32_t)((c % 3) * G_STAGE_HALVES) * 2;
        const int k0 = c * 32;
        cp_async16(da + so,      Xa + k0);
        cp_async16(da + so + 16, Xa + k0 + 8);
        cp_async16(db + so,      Wb + k0);
        cp_async16(db + so + 16, Wb + k0 + 8);
        cp_commit();
    };

#pragma unroll
    for (int i = 0; i < 16; ++i)
#pragma unroll
        for (int j = 0; j < 4; ++j) g.acc[i][j] = 0.0f;

    issue(0);
    issue(1);

    for (int c = 0; c < G_NCHUNK; ++c) {
        cp_wait<1>();
        __syncthreads();
        if (c + 2 < G_NCHUNK) issue(c + 2);
        else cp_commit();

        const __half* As = gsh + (c % 3) * G_STAGE_HALVES;
        const __half* Bs = As + 128 * RS;

#pragma unroll
        for (int ks = 0; ks < 2; ++ks) {
            const int kk = ks * 16 + 2 * g.qcol;
            uint32_t af[4][4];
            uint32_t bf[4][2];
#pragma unroll
            for (int mt = 0; mt < 4; ++mt) {
                const __half* ap = As + (g.warp_m + mt * 16 + g.qrow) * RS + kk;
                af[mt][0] = *(const uint32_t*)ap;
                af[mt][1] = *(const uint32_t*)(ap + 8 * RS);
                af[mt][2] = *(const uint32_t*)(ap + 8);
                af[mt][3] = *(const uint32_t*)(ap + 8 * RS + 8);
            }
#pragma unroll
            for (int nt = 0; nt < 4; ++nt) {
                const __half* bp = Bs + (g.warp_n + nt * 8 + g.qrow) * RS + kk;
                bf[nt][0] = *(const uint32_t*)bp;
                bf[nt][1] = *(const uint32_t*)(bp + 8);
            }
#pragma unroll
            for (int mt = 0; mt < 4; ++mt)
#pragma unroll
                for (int nt = 0; nt < 4; ++nt)
                    mma_f16(g.acc[mt * 4 + nt][0], g.acc[mt * 4 + nt][1],
                            g.acc[mt * 4 + nt][2], g.acc[mt * 4 + nt][3],
                            af[mt][0], af[mt][1], af[mt][2], af[mt][3],
                            bf[nt][0], bf[nt][1]);
        }
    }
}

// Fused Q/K/V projections. z=0/1 -> fp16 [b][s][h] pi-store (hd);
// z=2 -> fp16 V^T store with pi-permuted s.
__global__ __launch_bounds__(256, 2)
void qkv_gemm_kernel(const __half* __restrict__ inh, const __half* __restrict__ wh,
                     const float* __restrict__ bq, const float* __restrict__ bk,
                     const float* __restrict__ bv,
                     __half* __restrict__ Cq, __half* __restrict__ Ck,
                     __half* __restrict__ Cvt)
{
    const int z = blockIdx.z;
    const __half* X = inh + (size_t)z * M_ * H_;
    const __half* W = wh + (size_t)z * H_ * H_;
    const float* bias = (z == 0) ? bq : (z == 1) ? bk : bv;

    GemmCtx g;
    gemm_compute(g, X, W);

    if (z < 2) {
        __half* C = (z == 0) ? Cq : Ck;
#pragma unroll
        for (int mt = 0; mt < 4; ++mt) {
            int row = g.m0 + g.warp_m + mt * 16 + g.qrow;
#pragma unroll
            for (int nt = 0; nt < 4; ++nt) {
                int col = g.n0 + g.warp_n + nt * 8 + 2 * g.qcol;   // natural col
                // pi pos within 16-block: old (2q,2q+1)->4q ; +8 -> +2
                int ncol = (col & ~15) + 4 * g.qcol + ((nt & 1) << 1);
                float b0v = __ldg(&bias[col]);
                float b1v = __ldg(&bias[col + 1]);
                uint32_t h0v = packh2(g.acc[mt * 4 + nt][0] + b0v,
                                      g.acc[mt * 4 + nt][1] + b1v);
                uint32_t h1v = packh2(g.acc[mt * 4 + nt][2] + b0v,
                                      g.acc[mt * 4 + nt][3] + b1v);
                *(uint32_t*)(C + (size_t)row * H_ + ncol)       = h0v;
                *(uint32_t*)(C + (size_t)(row + 8) * H_ + ncol) = h1v;
            }
        }
    } else {
        // V transposed: [b][h][hd][s], s pi-permuted within 16-blocks
#pragma unroll
        for (int mt = 0; mt < 4; ++mt) {
            int srow = g.m0 + g.warp_m + mt * 16 + g.qrow;
            int bb = srow >> 11, s = srow & 2047;
            int j = s & 15;                       // 0..7 here (qrow 0..7)
            int pos0 = (s & ~15) + 4 * (j >> 1) + (j & 1);   // old row j
            // old row j+8 -> pos0 + 2
#pragma unroll
            for (int nt = 0; nt < 4; ++nt) {
                int col = g.n0 + g.warp_n + nt * 8 + 2 * g.qcol;
                float b0v = __ldg(&bias[col]);
                float b1v = __ldg(&bias[col + 1]);
                int hh = col >> 6, hd = col & 63;
                __half* p = Cvt + ((size_t)(bb * NH_ + hh) * HD_ + hd) * S_;
                p[pos0]          = __float2half_rn(g.acc[mt * 4 + nt][0] + b0v);
                p[S_ + pos0]     = __float2half_rn(g.acc[mt * 4 + nt][1] + b1v);
                p[pos0 + 2]      = __float2half_rn(g.acc[mt * 4 + nt][2] + b0v);
                p[S_ + pos0 + 2] = __float2half_rn(g.acc[mt * 4 + nt][3] + b1v);
            }
        }
    }
}

__global__ __launch_bounds__(256, 2)
void out_gemm_kernel(const __half* __restrict__ X, const __half* __restrict__ wh,
                     const float* __restrict__ bias, float* __restrict__ C)
{
    GemmCtx g;
    gemm_compute(g, X, wh + (size_t)3 * H_ * H_);
#pragma unroll
    for (int mt = 0; mt < 4; ++mt) {
        int row = g.m0 + g.warp_m + mt * 16 + g.qrow;
#pragma unroll
        for (int nt = 0; nt < 4; ++nt) {
            int col = g.n0 + g.warp_n + nt * 8 + 2 * g.qcol;
            float b0v = __ldg(&bias[col]);
            float b1v = __ldg(&bias[col + 1]);
            *(float2*)(C + (size_t)row * H_ + col) =
                make_float2(g.acc[mt * 4 + nt][0] + b0v, g.acc[mt * 4 + nt][1] + b1v);
            *(float2*)(C + (size_t)(row + 8) * H_ + col) =
                make_float2(g.acc[mt * 4 + nt][2] + b0v, g.acc[mt * 4 + nt][3] + b1v);
        }
    }
}

// ===========================================================================
// fp16 mma flash attention. CTA: 128 Q rows, 8 warps. KV chunk 64,
// 3-stage cp.async, ONE barrier per chunk, occ 2.
// pi-permuted operands + RSTH=80 (40 words == 8 mod 32): LDS.64 fragment
// loads, conflict-free (phase banks 8*gr+2qc all distinct).
// ===========================================================================
#define KVC 64
#define NCH (S_ / KVC)          // 32
#define RSTH 80                 // smem row stride in halves (64 data + 16 pad)
#define TILE_HALVES (64 * RSTH)               // 5120
#define STG_HALVES  (2 * TILE_HALVES)         // K + Vt, one stage = 10240
#define ATT_SMEM_BYTES (3 * STG_HALVES * 2)   // 61440

__global__ __launch_bounds__(256, 2)
void attn_mma_kernel(const __half* __restrict__ Qh, const __half* __restrict__ Kh,
                     const __half* __restrict__ Vth, const __half* __restrict__ FMh,
                     __half* __restrict__ Oh)
{
    extern __shared__ __half smh[];
    const uint32_t sb = smem_u32(smh);

    const int tid  = threadIdx.x;
    const int wid  = tid >> 5;
    const int lane = tid & 31;
    const int gr   = lane >> 2;    // 0..7
    const int qc   = lane & 3;     // 0..3
    const int q0   = blockIdx.x * 128;
    const int h    = blockIdx.y;
    const int b    = blockIdx.z;
    const int wrow = wid * 16;
    const float L2E = 1.44269504f;

    const size_t base   = (size_t)b * S_ * H_ + (size_t)h * HD_;       // Q/K halves
    const size_t vtbase = (size_t)(b * NH_ + h) * HD_ * S_;            // Vt halves

    // Q fragments from pi-permuted Qh: uint2 at pos ks*16+4qc = (a_klo, a_khi)
    uint32_t qf[4][4];
    {
        const __half* Qr0 = Qh + base + (size_t)(q0 + wrow + gr) * H_;
        const __half* Qr1 = Qh + base + (size_t)(q0 + wrow + gr + 8) * H_;
#pragma unroll
        for (int ks = 0; ks < 4; ++ks) {
            int c = ks * 16 + 4 * qc;
            uint2 lo = *(const uint2*)(Qr0 + c);
            uint2 hi = *(const uint2*)(Qr1 + c);
            qf[ks][0] = lo.x; qf[ks][1] = hi.x;
            qf[ks][2] = lo.y; qf[ks][3] = hi.y;
        }
    }

    float oacc[8][4];
#pragma unroll
    for (int i = 0; i < 8; ++i)
#pragma unroll
        for (int j = 0; j < 4; ++j) oacc[i][j] = 0.0f;
    float m_lo = -1e30f, m_hi = -1e30f, l_lo = 0.0f, l_hi = 0.0f;   // l lane-local

    const int prow = tid >> 3;          // 0..31
    const int pch  = tid & 7;           // 0..7

    auto issue_chunk = [&](int c) {
        const uint32_t kb = sb + (uint32_t)((c % 3) * STG_HALVES) * 2;
        const uint32_t vb = kb + (uint32_t)TILE_HALVES * 2;
        const int k0 = c * KVC;
#pragma unroll
        for (int it = 0; it < 2; ++it) {
            int r = prow + it * 32;     // 0..63
            cp_async16(kb + (uint32_t)(r * RSTH + pch * 8) * 2,
                       Kh + base + (size_t)(k0 + r) * H_ + pch * 8);
            cp_async16(vb + (uint32_t)(r * RSTH + pch * 8) * 2,
                       Vth + vtbase + (size_t)r * S_ + k0 + pch * 8);
        }
        cp_commit();
    };

    issue_chunk(0);
    issue_chunk(1);

    const size_t fmbase_lo = ((size_t)b * S_ + (q0 + wrow + gr)) * S_;
    const size_t fmbase_hi = fmbase_lo + (size_t)8 * S_;

    for (int c = 0; c < NCH; ++c) {
        cp_wait<1>();          // group c complete (groups retire in order)
        __syncthreads();       // data visible + all warps finished chunk c-1
        if (c + 2 < NCH) issue_chunk(c + 2);   // writes stage (c-1)%3: safe
        else cp_commit();                       // keep group-count invariant

        const __half* Ks = smh + (c % 3) * STG_HALVES;
        const __half* Vs = Ks + TILE_HALVES;
        const int k0 = c * KVC;

        // ---- S = Q K^T (uint2 LDS.64 fragment loads) ----
        float sv[8][4];
#pragma unroll
        for (int i = 0; i < 8; ++i)
#pragma unroll
            for (int j = 0; j < 4; ++j) sv[i][j] = 0.0f;

#pragma unroll
        for (int ks = 0; ks < 4; ++ks) {
            const int kk = ks * 16 + 4 * qc;
#pragma unroll
            for (int nt = 0; nt < 8; ++nt) {
                uint2 bb = *(const uint2*)(Ks + (nt * 8 + gr) * RSTH + kk);
                mma_f16(sv[nt][0], sv[nt][1], sv[nt][2], sv[nt][3],
                        qf[ks][0], qf[ks][1], qf[ks][2], qf[ks][3], bb.x, bb.y);
            }
        }

        // ---- fused mask (fp16, streaming) + row max ----
        float tmax_lo = -1e30f, tmax_hi = -1e30f;
#pragma unroll
        for (int nt = 0; nt < 8; ++nt) {
            int colo = k0 + nt * 8 + 2 * qc;
            uint32_t ul = __ldcs((const uint32_t*)(FMh + fmbase_lo + colo));
            uint32_t uh = __ldcs((const uint32_t*)(FMh + fmbase_hi + colo));
            float2 fl = __half22float2(*(const __half2*)&ul);
            float2 fh = __half22float2(*(const __half2*)&uh);
            float s0 = (fl.x < 0.0f) ? -1e30f : sv[nt][0] * fl.x;
            float s1 = (fl.y < 0.0f) ? -1e30f : sv[nt][1] * fl.y;
            float s2 = (fh.x < 0.0f) ? -1e30f : sv[nt][2] * fh.x;
            float s3 = (fh.y < 0.0f) ? -1e30f : sv[nt][3] * fh.y;
            sv[nt][0] = s0; sv[nt][1] = s1; sv[nt][2] = s2; sv[nt][3] = s3;
            tmax_lo = fmaxf(tmax_lo, fmaxf(s0, s1));
            tmax_hi = fmaxf(tmax_hi, fmaxf(s2, s3));
        }
        tmax_lo = fmaxf(tmax_lo, __shfl_xor_sync(0xffffffffu, tmax_lo, 1));
        tmax_lo = fmaxf(tmax_lo, __shfl_xor_sync(0xffffffffu, tmax_lo, 2));
        tmax_hi = fmaxf(tmax_hi, __shfl_xor_sync(0xffffffffu, tmax_hi, 1));
        tmax_hi = fmaxf(tmax_hi, __shfl_xor_sync(0xffffffffu, tmax_hi, 2));

        float newm_lo = fmaxf(m_lo, tmax_lo);
        float newm_hi = fmaxf(m_hi, tmax_hi);
        float alpha_lo = __expf(m_lo - newm_lo);
        float alpha_hi = __expf(m_hi - newm_hi);
        m_lo = newm_lo; m_hi = newm_hi;

        // ---- exp via ex2.f16x2; lane-local l accumulation ----
        const float ml_lo = newm_lo * L2E;
        const float ml_hi = newm_hi * L2E;
        uint32_t plo[8], phi[8];
        float rs_lo = 0.0f, rs_hi = 0.0f;
#pragma unroll
        for (int nt = 0; nt < 8; ++nt) {
            float t0 = fmaf(sv[nt][0], L2E, -ml_lo);
            float t1 = fmaf(sv[nt][1], L2E, -ml_lo);
            float t2 = fmaf(sv[nt][2], L2E, -ml_hi);
            float t3 = fmaf(sv[nt][3], L2E, -ml_hi);
            uint32_t pl = ex2_h2(packh2(t0, t1));
            uint32_t ph = ex2_h2(packh2(t2, t3));
            plo[nt] = pl; phi[nt] = ph;
            float2 f2l = __half22float2(*(const __half2*)&pl);
            float2 f2h = __half22float2(*(const __half2*)&ph);
            rs_lo += f2l.x + f2l.y;
            rs_hi += f2h.x + f2h.y;
        }
        l_lo = l_lo * alpha_lo + rs_lo;
        l_hi = l_hi * alpha_hi + rs_hi;

        // ---- rescale O ----
#pragma unroll
        for (int nt = 0; nt < 8; ++nt) {
            oacc[nt][0] *= alpha_lo; oacc[nt][1] *= alpha_lo;
            oacc[nt][2] *= alpha_hi; oacc[nt][3] *= alpha_hi;
        }

        // ---- O += P V : packed P pairs == A-fragments; Vt s-pi -> uint2 ----
#pragma unroll
        for (int t = 0; t < 4; ++t) {
            uint32_t a0 = plo[2 * t];
            uint32_t a1 = phi[2 * t];
            uint32_t a2 = plo[2 * t + 1];
            uint32_t a3 = phi[2 * t + 1];
            const int kk = t * 16 + 4 * qc;
#pragma unroll
            for (int nt = 0; nt < 8; ++nt) {
                uint2 bb = *(const uint2*)(Vs + (nt * 8 + gr) * RSTH + kk);
                mma_f16(oacc[nt][0], oacc[nt][1], oacc[nt][2], oacc[nt][3],
                        a0, a1, a2, a3, bb.x, bb.y);
            }
        }
    }

    // ---- final l reduction + epilogue: natural-order fp16 AO ----
    l_lo += __shfl_xor_sync(0xffffffffu, l_lo, 1);
    l_lo += __shfl_xor_sync(0xffffffffu, l_lo, 2);
    l_hi += __shfl_xor_sync(0xffffffffu, l_hi, 1);
    l_hi += __shfl_xor_sync(0xffffffffu, l_hi, 2);
    float inv_lo = 1.0f / l_lo;
    float inv_hi = 1.0f / l_hi;
    __half* Or0 = Oh + base + (size_t)(q0 + wrow + gr) * H_;
    __half* Or1 = Oh + base + (size_t)(q0 + wrow + gr + 8) * H_;
#pragma unroll
    for (int nt = 0; nt < 8; ++nt) {
        int col = nt * 8 + 2 * qc;
        *(uint32_t*)(Or0 + col) = packh2(oacc[nt][0] * inv_lo, oacc[nt][1] * inv_lo);
        *(uint32_t*)(Or1 + col) = packh2(oacc[nt][2] * inv_hi, oacc[nt][3] * inv_hi);
    }
}

// ---------------------------------------------------------------------------
extern "C" void kernel_launch(void* const* d_in, const int* in_sizes, int n_in,
                              void* d_out, int out_size)
{
    const float* query = (const float*)d_in[0];
    const float* key   = (const float*)d_in[1];
    const float* value = (const float*)d_in[2];
    const int*   mask  = (const int*)d_in[3];
    const float* smask = (const float*)d_in[4];
    const float* Wq = (const float*)d_in[5];
    const float* bq = (const float*)d_in[6];
    const float* Wk = (const float*)d_in[7];
    const float* bk = (const float*)d_in[8];
    const float* Wv = (const float*)d_in[9];
    const float* bv = (const float*)d_in[10];
    const float* Wo = (const float*)d_in[11];
    const float* bo = (const float*)d_in[12];
    float* out = (float*)d_out;

    __half *ginh, *gwh, *gqh, *gkh, *gvt, *gaoh, *gfmh;
    cudaGetSymbolAddress((void**)&ginh, g_INh);
    cudaGetSymbolAddress((void**)&gwh,  g_Wh);
    cudaGetSymbolAddress((void**)&gqh,  g_Qh);
    cudaGetSymbolAddress((void**)&gkh,  g_Kh);
    cudaGetSymbolAddress((void**)&gvt,  g_Vt);
    cudaGetSymbolAddress((void**)&gaoh, g_AOh);
    cudaGetSymbolAddress((void**)&gfmh, g_FMh);

    cudaFuncSetAttribute(qkv_gemm_kernel,
                         cudaFuncAttributeMaxDynamicSharedMemorySize, G_SMEM_BYTES);
    cudaFuncSetAttribute(out_gemm_kernel,
                         cudaFuncAttributeMaxDynamicSharedMemorySize, G_SMEM_BYTES);
    cudaFuncSetAttribute(attn_mma_kernel,
                         cudaFuncAttributeMaxDynamicSharedMemorySize, ATT_SMEM_BYTES);

    dim3 cgrid(M_ * H_ / 4 / 256, 7);      // (4096, 7)
    cvt_kernel<<<cgrid, 256>>>(query, key, value, Wq, Wk, Wv, Wo, ginh, gwh);

    fuse_mask_kernel<<<(B_ * S_ * S_ / 4) / 256, 256>>>(mask, smask, gfmh);

    dim3 gblk(256);
    dim3 qkvgrid(H_ / 128, M_ / 128, 3);   // (8, 32, 3)
    qkv_gemm_kernel<<<qkvgrid, gblk, G_SMEM_BYTES>>>(
        ginh, gwh, bq, bk, bv, gqh, gkh, gvt);

    dim3 agrid(S_ / 128, NH_, B_);         // (16, 16, 2)
    attn_mma_kernel<<<agrid, 256, ATT_SMEM_BYTES>>>(gqh, gkh, gvt, gfmh, gaoh);

    dim3 ogrid(H_ / 128, M_ / 128);        // (8, 32)
    out_gemm_kernel<<<ogrid, gblk, G_SMEM_BYTES>>>(gaoh, gwh, bo, out);
}